// round 6
// baseline (speedup 1.0000x reference)
#include <cuda_runtime.h>
#include <cuda_bf16.h>
#include <stdint.h>

#define NB   8
#define CC   64
#define HWSZ 65536   // 256*256

// ---------------- scratch (static device globals; no allocation) ----------------
__device__ __nv_bfloat16 d_t1[(size_t)NB * 128 * HWSZ];   // 128 MB: pw1 out, [n][o<128][hw]
__device__ __nv_bfloat16 d_gate[(size_t)NB * CC * HWSZ];  //  64 MB: gated dwconv out
__device__ float         d_xmid[(size_t)NB * CC * HWSZ];  // 128 MB: x + beta1*y
__device__ float d_ln1_scale[NB * CC], d_ln1_shift[NB * CC];
__device__ float d_ln2_scale[NB * CC], d_ln2_shift[NB * CC];
__device__ float d_sca_part[NB * CC * 64];                // per-(n,c) per-tile partials
__device__ float d_ln2_pS[NB * CC * 512], d_ln2_pQ[NB * CC * 512];
__device__ float d_sca_scale[NB * CC];

// ---------------- helpers ----------------
__device__ __forceinline__ void mma_bf16(float d[4], const uint32_t a[4], uint32_t b0, uint32_t b1) {
    asm volatile(
        "mma.sync.aligned.m16n8k16.row.col.f32.bf16.bf16.f32 "
        "{%0,%1,%2,%3},{%4,%5,%6,%7},{%8,%9},{%0,%1,%2,%3};\n"
        : "+f"(d[0]), "+f"(d[1]), "+f"(d[2]), "+f"(d[3])
        : "r"(a[0]), "r"(a[1]), "r"(a[2]), "r"(a[3]), "r"(b0), "r"(b1));
}
__device__ __forceinline__ uint32_t ldh2(const __nv_bfloat16* p) {
    return *reinterpret_cast<const uint32_t*>(p);
}

// ---------------- K0: ln1 stats per (n,c) ----------------
__global__ void k_ln1(const float* __restrict__ x, const float* __restrict__ w,
                      const float* __restrict__ b) {
    int nc = blockIdx.x;
    const float4* p = reinterpret_cast<const float4*>(x + (size_t)nc * HWSZ);
    float s = 0.f, q = 0.f;
    for (int i = threadIdx.x; i < HWSZ / 4; i += blockDim.x) {
        float4 v = p[i];
        s += (v.x + v.y) + (v.z + v.w);
        q += (v.x * v.x + v.y * v.y) + (v.z * v.z + v.w * v.w);
    }
    __shared__ float ss[8], sq[8];
    for (int o = 16; o; o >>= 1) {
        s += __shfl_down_sync(0xffffffffu, s, o);
        q += __shfl_down_sync(0xffffffffu, q, o);
    }
    int wid = threadIdx.x >> 5, lane = threadIdx.x & 31;
    if (!lane) { ss[wid] = s; sq[wid] = q; }
    __syncthreads();
    if (threadIdx.x == 0) {
        s = 0.f; q = 0.f;
        for (int i = 0; i < 8; i++) { s += ss[i]; q += sq[i]; }
        float mean = s * (1.f / HWSZ);
        float var  = q * (1.f / HWSZ) - mean * mean;
        float rstd = rsqrtf(var + 1e-6f);
        int c = nc & (CC - 1);
        float sc = rstd * w[c];
        d_ln1_scale[nc] = sc;
        d_ln1_shift[nc] = b[c] - mean * sc;
    }
}

// ---------------- K1: normalize -> pw1 (64 -> 128), bf16 MMA ----------------
__global__ __launch_bounds__(256) void k_pw1(const float* __restrict__ x,
                                             const float* __restrict__ w1,
                                             const float* __restrict__ bias) {
    __shared__ __align__(16) unsigned char raw[36864];
    __nv_bfloat16 (*A)[72]  = reinterpret_cast<__nv_bfloat16(*)[72]>(raw);                // 128px x 64c
    __nv_bfloat16 (*W)[72]  = reinterpret_cast<__nv_bfloat16(*)[72]>(raw + 128 * 72 * 2); // 128o x 64c
    __nv_bfloat16 (*O)[136] = reinterpret_cast<__nv_bfloat16(*)[136]>(raw);               // aliases after sync

    int tid = threadIdx.x;
    int blk = blockIdx.x;
    int n   = blk >> 9;
    int hw0 = (blk & 511) << 7;
    const float* xb = x + (size_t)n * CC * HWSZ + hw0;

    for (int i = tid; i < CC * 128; i += 256) {
        int c = i >> 7, pl = i & 127;
        int nc = n * CC + c;
        float v = xb[(size_t)c * HWSZ + pl];
        A[pl][c] = __float2bfloat16(fmaf(v, d_ln1_scale[nc], d_ln1_shift[nc]));
    }
    for (int i = tid; i < 128 * CC; i += 256)
        W[i >> 6][i & 63] = __float2bfloat16(w1[i]);
    __syncthreads();

    int warp = tid >> 5, lane = tid & 31, g = lane >> 2, tg = lane & 3;
    int pbase = (warp >> 1) << 5;  // 4 pixel-groups of 32
    int obase = (warp & 1) << 6;   // 2 out-halves of 64
    float acc[2][8][4];
#pragma unroll
    for (int mt = 0; mt < 2; mt++)
#pragma unroll
        for (int nt = 0; nt < 8; nt++)
#pragma unroll
            for (int r = 0; r < 4; r++) acc[mt][nt][r] = 0.f;

#pragma unroll
    for (int kk = 0; kk < 4; kk++) {
        int k0 = kk << 4;
        uint32_t a[2][4];
#pragma unroll
        for (int mt = 0; mt < 2; mt++) {
            const __nv_bfloat16* ap = &A[pbase + (mt << 4) + g][k0 + (tg << 1)];
            a[mt][0] = ldh2(ap);
            a[mt][1] = ldh2(ap + 8 * 72);
            a[mt][2] = ldh2(ap + 8);
            a[mt][3] = ldh2(ap + 8 * 72 + 8);
        }
#pragma unroll
        for (int nt = 0; nt < 8; nt++) {
            const __nv_bfloat16* bp = &W[obase + (nt << 3) + g][k0 + (tg << 1)];
            uint32_t b0 = ldh2(bp), b1v = ldh2(bp + 8);
            mma_bf16(acc[0][nt], a[0], b0, b1v);
            mma_bf16(acc[1][nt], a[1], b0, b1v);
        }
    }
    __syncthreads();
#pragma unroll
    for (int mt = 0; mt < 2; mt++)
#pragma unroll
        for (int nt = 0; nt < 8; nt++) {
            int p = pbase + (mt << 4) + g;
            int o = obase + (nt << 3) + (tg << 1);
            float bo0 = bias[o], bo1 = bias[o + 1];
            O[o][p]         = __float2bfloat16(acc[mt][nt][0] + bo0);
            O[o + 1][p]     = __float2bfloat16(acc[mt][nt][1] + bo1);
            O[o][p + 8]     = __float2bfloat16(acc[mt][nt][2] + bo0);
            O[o + 1][p + 8] = __float2bfloat16(acc[mt][nt][3] + bo1);
        }
    __syncthreads();
    __nv_bfloat16* t1b = d_t1 + (size_t)n * 128 * HWSZ + hw0;
    for (int i = tid; i < 128 * 64; i += 256) {
        int o = i >> 6, pp = (i & 63) << 1;
        *reinterpret_cast<__nv_bfloat162*>(t1b + (size_t)o * HWSZ + pp) =
            *reinterpret_cast<__nv_bfloat162*>(&O[o][pp]);
    }
}

// ---------------- K2: depthwise 3x3 + SimpleGate + SCA partial sums ----------------
__global__ __launch_bounds__(256) void k_dw(const float* __restrict__ dww,
                                            const float* __restrict__ dwb) {
    __shared__ float t0[18][66];
    __shared__ float t1s[18][66];
    __shared__ float red[8];
    int bx   = blockIdx.x;
    int tx4  = bx & 3;           // x tile (64 wide)
    int ty16 = (bx >> 2) & 15;   // y tile (16 tall)
    int c    = (bx >> 6) & 63;
    int n    = bx >> 12;
    int tid  = threadIdx.x;
    const __nv_bfloat16* p0 = d_t1 + (size_t)(n * 128 + c) * HWSZ;
    const __nv_bfloat16* p1 = d_t1 + (size_t)(n * 128 + c + 64) * HWSZ;
    int gx0 = tx4 << 6, gy0 = ty16 << 4;

    for (int i = tid; i < 2 * 18 * 66; i += 256) {
        int ch  = i / (18 * 66);
        int rem = i - ch * (18 * 66);
        int r   = rem / 66;
        int col = rem - r * 66;
        int gy = gy0 + r - 1, gx = gx0 + col - 1;
        float v = 0.f;
        if ((unsigned)gy < 256u && (unsigned)gx < 256u) {
            const __nv_bfloat16* pp = ch ? p1 : p0;
            v = __bfloat162float(pp[gy * 256 + gx]);
        }
        (ch ? t1s : t0)[r][col] = v;
    }
    float w0[9], w1[9];
#pragma unroll
    for (int k = 0; k < 9; k++) {
        w0[k] = dww[c * 9 + k];
        w1[k] = dww[(c + 64) * 9 + k];
    }
    float db0 = dwb[c], db1 = dwb[c + 64];
    __syncthreads();

    int tx = tid & 63, tyb = tid >> 6;
    float psum = 0.f;
    __nv_bfloat16* gout = d_gate + (size_t)(n * 64 + c) * HWSZ;
#pragma unroll
    for (int j = 0; j < 4; j++) {
        int ty = (tyb << 2) + j;
        float s0 = db0, s1 = db1;
#pragma unroll
        for (int ky = 0; ky < 3; ky++)
#pragma unroll
            for (int kx = 0; kx < 3; kx++) {
                s0 += t0[ty + ky][tx + kx] * w0[ky * 3 + kx];
                s1 += t1s[ty + ky][tx + kx] * w1[ky * 3 + kx];
            }
        float v = s0 * s1;
        psum += v;
        gout[(gy0 + ty) * 256 + gx0 + tx] = __float2bfloat16(v);
    }
    for (int o = 16; o; o >>= 1) psum += __shfl_down_sync(0xffffffffu, psum, o);
    int lane = tid & 31, wid = tid >> 5;
    if (!lane) red[wid] = psum;
    __syncthreads();
    if (tid == 0) {
        float t = 0.f;
        for (int i = 0; i < 8; i++) t += red[i];
        d_sca_part[(n * 64 + c) * 64 + (bx & 63)] = t;   // deterministic slot
    }
}

// ---------------- K3: SCA  sigmoid(W s + b) ----------------
__global__ void k_sca(const float* __restrict__ sw, const float* __restrict__ sb) {
    __shared__ float s[NB * CC];
    int tid = threadIdx.x;   // 512
    {
        float t = 0.f;
        const float* p = d_sca_part + tid * 64;
        for (int i = 0; i < 64; i++) t += p[i];
        s[tid] = t * (1.f / HWSZ);
    }
    __syncthreads();
    int n = tid >> 6, o = tid & 63;
    float acc = sb[o];
    const float* wr = sw + o * 64;
    const float* sr = s + n * 64;
    for (int c = 0; c < 64; c++) acc = fmaf(wr[c], sr[c], acc);
    d_sca_scale[tid] = 1.f / (1.f + expf(-acc));
}

// ---------------- K4: scale -> pw2 (64->64) -> residual -> xmid + ln2 partials ----------------
__global__ __launch_bounds__(256) void k_pw2(const float* __restrict__ x,
                                             const float* __restrict__ w2,
                                             const float* __restrict__ b2,
                                             const float* __restrict__ beta1) {
    __shared__ __align__(16) unsigned char raw[33792];
    __nv_bfloat16 (*A)[72] = reinterpret_cast<__nv_bfloat16(*)[72]>(raw);                // 128px x 64c
    __nv_bfloat16 (*W)[72] = reinterpret_cast<__nv_bfloat16(*)[72]>(raw + 128 * 72 * 2); // 64o x 64c
    float (*O)[132]        = reinterpret_cast<float(*)[132]>(raw);                       // aliases after sync
    __shared__ float psA[64][4], psB[64][4];

    int tid = threadIdx.x;
    int blk = blockIdx.x;
    int n   = blk >> 9;
    int hw0 = (blk & 511) << 7;

    for (int i = tid; i < 64 * 128; i += 256) {
        int c = i >> 7, pl = i & 127;
        float v = __bfloat162float(d_gate[(size_t)(n * 64 + c) * HWSZ + hw0 + pl]) *
                  d_sca_scale[n * 64 + c];
        A[pl][c] = __float2bfloat16(v);
    }
    for (int i = tid; i < 64 * 64; i += 256)
        W[i >> 6][i & 63] = __float2bfloat16(w2[i]);
    __syncthreads();

    int warp = tid >> 5, lane = tid & 31, g = lane >> 2, tg = lane & 3;
    int pbase = (warp >> 1) << 5;
    int obase = (warp & 1) << 5;  // 2 out-halves of 32
    float acc[2][4][4];
#pragma unroll
    for (int mt = 0; mt < 2; mt++)
#pragma unroll
        for (int nt = 0; nt < 4; nt++)
#pragma unroll
            for (int r = 0; r < 4; r++) acc[mt][nt][r] = 0.f;

#pragma unroll
    for (int kk = 0; kk < 4; kk++) {
        int k0 = kk << 4;
        uint32_t a[2][4];
#pragma unroll
        for (int mt = 0; mt < 2; mt++) {
            const __nv_bfloat16* ap = &A[pbase + (mt << 4) + g][k0 + (tg << 1)];
            a[mt][0] = ldh2(ap);
            a[mt][1] = ldh2(ap + 8 * 72);
            a[mt][2] = ldh2(ap + 8);
            a[mt][3] = ldh2(ap + 8 * 72 + 8);
        }
#pragma unroll
        for (int nt = 0; nt < 4; nt++) {
            const __nv_bfloat16* bp = &W[obase + (nt << 3) + g][k0 + (tg << 1)];
            uint32_t b0 = ldh2(bp), b1v = ldh2(bp + 8);
            mma_bf16(acc[0][nt], a[0], b0, b1v);
            mma_bf16(acc[1][nt], a[1], b0, b1v);
        }
    }
    __syncthreads();
#pragma unroll
    for (int mt = 0; mt < 2; mt++)
#pragma unroll
        for (int nt = 0; nt < 4; nt++) {
            int p = pbase + (mt << 4) + g;
            int o = obase + (nt << 3) + (tg << 1);
            O[o][p]         = acc[mt][nt][0] + b2[o];
            O[o + 1][p]     = acc[mt][nt][1] + b2[o + 1];
            O[o][p + 8]     = acc[mt][nt][2] + b2[o];
            O[o + 1][p + 8] = acc[mt][nt][3] + b2[o + 1];
        }
    __syncthreads();
    const float* xb = x + (size_t)n * 64 * HWSZ + hw0;
    float* xm = d_xmid + (size_t)n * 64 * HWSZ + hw0;
    for (int i = tid; i < 64 * 128; i += 256) {
        int o = i >> 7, p = i & 127;
        float v = xb[(size_t)o * HWSZ + p] + beta1[o] * O[o][p];
        xm[(size_t)o * HWSZ + p] = v;
        O[o][p] = v;   // keep in smem for stats
    }
    __syncthreads();
    {
        int o = tid >> 2, seg = (tid & 3) << 5;
        float s = 0.f, q = 0.f;
        for (int j = 0; j < 32; j++) {
            float v = O[o][seg + j];
            s += v; q += v * v;
        }
        psA[o][tid & 3] = s; psB[o][tid & 3] = q;
    }
    __syncthreads();
    if (tid < 64) {
        float s = psA[tid][0] + psA[tid][1] + psA[tid][2] + psA[tid][3];
        float q = psB[tid][0] + psB[tid][1] + psB[tid][2] + psB[tid][3];
        size_t slot = (size_t)(n * 64 + tid) * 512 + (blk & 511);
        d_ln2_pS[slot] = s;
        d_ln2_pQ[slot] = q;
    }
}

// ---------------- K5: ln2 finalize (deterministic fixed-order sum) ----------------
__global__ void k_ln2fin(const float* __restrict__ w, const float* __restrict__ b) {
    int nc = threadIdx.x;  // 512
    float s = 0.f, q = 0.f;
    const float* pS = d_ln2_pS + (size_t)nc * 512;
    const float* pQ = d_ln2_pQ + (size_t)nc * 512;
    for (int i = 0; i < 512; i++) { s += pS[i]; q += pQ[i]; }
    float mean = s * (1.f / HWSZ);
    float var  = q * (1.f / HWSZ) - mean * mean;
    float rstd = rsqrtf(var + 1e-6f);
    int c = nc & 63;
    float sc = rstd * w[c];
    d_ln2_scale[nc] = sc;
    d_ln2_shift[nc] = b[c] - mean * sc;
}

// ---------------- K6: normalize -> pw3 -> gate -> pw4 -> residual -> out ----------------
__global__ __launch_bounds__(256) void k_pw34(const float* __restrict__ w3,
                                              const float* __restrict__ b3,
                                              const float* __restrict__ w4,
                                              const float* __restrict__ b4,
                                              const float* __restrict__ beta2,
                                              float* __restrict__ out) {
    extern __shared__ __align__(16) unsigned char dyn[];
    __nv_bfloat16 (*W3)[72] = reinterpret_cast<__nv_bfloat16(*)[72]>(dyn);            // 128o x 64c
    __nv_bfloat16 (*W4)[72] = reinterpret_cast<__nv_bfloat16(*)[72]>(dyn + 18432);    // 64o x 64c
    __nv_bfloat16 (*A)[72]  = reinterpret_cast<__nv_bfloat16(*)[72]>(dyn + 27648);    // 128px x 64c
    __nv_bfloat16 (*U)[136] = reinterpret_cast<__nv_bfloat16(*)[136]>(dyn + 46080);   // 128px x 128o
    float (*Z)[132]         = reinterpret_cast<float(*)[132]>(dyn + 46080);           // aliases U

    int tid = threadIdx.x;
    int blk = blockIdx.x;
    int n   = blk >> 9;
    int hw0 = (blk & 511) << 7;
    const float* xm = d_xmid + (size_t)n * 64 * HWSZ + hw0;

    for (int i = tid; i < 128 * 64; i += 256) W3[i >> 6][i & 63] = __float2bfloat16(w3[i]);
    for (int i = tid; i < 64 * 64; i += 256)  W4[i >> 6][i & 63] = __float2bfloat16(w4[i]);
    for (int i = tid; i < 64 * 128; i += 256) {
        int c = i >> 7, pl = i & 127;
        int nc = n * 64 + c;
        A[pl][c] = __float2bfloat16(fmaf(xm[(size_t)c * HWSZ + pl], d_ln2_scale[nc], d_ln2_shift[nc]));
    }
    __syncthreads();

    int warp = tid >> 5, lane = tid & 31, g = lane >> 2, tg = lane & 3;
    int pbase = (warp >> 1) << 5;
    int obase = (warp & 1) << 6;

    // ---- GEMM1: u = A @ W3^T  (128px x 128out) ----
    {
        float acc[2][8][4];
#pragma unroll
        for (int mt = 0; mt < 2; mt++)
#pragma unroll
            for (int nt = 0; nt < 8; nt++)
#pragma unroll
                for (int r = 0; r < 4; r++) acc[mt][nt][r] = 0.f;
#pragma unroll
        for (int kk = 0; kk < 4; kk++) {
            int k0 = kk << 4;
            uint32_t a[2][4];
#pragma unroll
            for (int mt = 0; mt < 2; mt++) {
                const __nv_bfloat16* ap = &A[pbase + (mt << 4) + g][k0 + (tg << 1)];
                a[mt][0] = ldh2(ap);
                a[mt][1] = ldh2(ap + 8 * 72);
                a[mt][2] = ldh2(ap + 8);
                a[mt][3] = ldh2(ap + 8 * 72 + 8);
            }
#pragma unroll
            for (int nt = 0; nt < 8; nt++) {
                const __nv_bfloat16* bp = &W3[obase + (nt << 3) + g][k0 + (tg << 1)];
                uint32_t b0 = ldh2(bp), b1v = ldh2(bp + 8);
                mma_bf16(acc[0][nt], a[0], b0, b1v);
                mma_bf16(acc[1][nt], a[1], b0, b1v);
            }
        }
        __syncthreads();   // A no longer needed; U region distinct anyway
#pragma unroll
        for (int mt = 0; mt < 2; mt++)
#pragma unroll
            for (int nt = 0; nt < 8; nt++) {
                int p = pbase + (mt << 4) + g;
                int o = obase + (nt << 3) + (tg << 1);
                float bo0 = b3[o], bo1 = b3[o + 1];
                __nv_bfloat162 lo, hi;
                lo.x = __float2bfloat16(acc[mt][nt][0] + bo0);
                lo.y = __float2bfloat16(acc[mt][nt][1] + bo1);
                hi.x = __float2bfloat16(acc[mt][nt][2] + bo0);
                hi.y = __float2bfloat16(acc[mt][nt][3] + bo1);
                *reinterpret_cast<__nv_bfloat162*>(&U[p][o])     = lo;
                *reinterpret_cast<__nv_bfloat162*>(&U[p + 8][o]) = hi;
            }
    }
    __syncthreads();

    // ---- GEMM2: z = gate(U) @ W4^T  (128px x 64out), gate fused into fragment build ----
    int obase2 = (warp & 1) << 5;
    float acc2[2][4][4];
#pragma unroll
    for (int mt = 0; mt < 2; mt++)
#pragma unroll
        for (int nt = 0; nt < 4; nt++)
#pragma unroll
            for (int r = 0; r < 4; r++) acc2[mt][nt][r] = 0.f;
#pragma unroll
    for (int kk = 0; kk < 4; kk++) {
        int k0 = kk << 4;
        uint32_t a2[2][4];
#pragma unroll
        for (int mt = 0; mt < 2; mt++) {
            int p = pbase + (mt << 4) + g;
            const __nv_bfloat16* r0 = &U[p][k0 + (tg << 1)];
            const __nv_bfloat16* r1 = &U[p + 8][k0 + (tg << 1)];
            __nv_bfloat162 v;
            v = __hmul2(*reinterpret_cast<const __nv_bfloat162*>(r0),
                        *reinterpret_cast<const __nv_bfloat162*>(r0 + 64));
            a2[mt][0] = *reinterpret_cast<uint32_t*>(&v);
            v = __hmul2(*reinterpret_cast<const __nv_bfloat162*>(r1),
                        *reinterpret_cast<const __nv_bfloat162*>(r1 + 64));
            a2[mt][1] = *reinterpret_cast<uint32_t*>(&v);
            v = __hmul2(*reinterpret_cast<const __nv_bfloat162*>(r0 + 8),
                        *reinterpret_cast<const __nv_bfloat162*>(r0 + 72));
            a2[mt][2] = *reinterpret_cast<uint32_t*>(&v);
            v = __hmul2(*reinterpret_cast<const __nv_bfloat162*>(r1 + 8),
                        *reinterpret_cast<const __nv_bfloat162*>(r1 + 72));
            a2[mt][3] = *reinterpret_cast<uint32_t*>(&v);
        }
#pragma unroll
        for (int nt = 0; nt < 4; nt++) {
            const __nv_bfloat16* bp = &W4[obase2 + (nt << 3) + g][k0 + (tg << 1)];
            uint32_t b0 = ldh2(bp), b1v = ldh2(bp + 8);
            mma_bf16(acc2[0][nt], a2[0], b0, b1v);
            mma_bf16(acc2[1][nt], a2[1], b0, b1v);
        }
    }
    __syncthreads();  // all U reads done before Z (alias) overwrite
#pragma unroll
    for (int mt = 0; mt < 2; mt++)
#pragma unroll
        for (int nt = 0; nt < 4; nt++) {
            int p = pbase + (mt << 4) + g;
            int o = obase2 + (nt << 3) + (tg << 1);
            Z[o][p]         = acc2[mt][nt][0] + b4[o];
            Z[o + 1][p]     = acc2[mt][nt][1] + b4[o + 1];
            Z[o][p + 8]     = acc2[mt][nt][2] + b4[o];
            Z[o + 1][p + 8] = acc2[mt][nt][3] + b4[o + 1];
        }
    __syncthreads();
    float* ob = out + (size_t)n * 64 * HWSZ + hw0;
    for (int i = tid; i < 64 * 128; i += 256) {
        int o = i >> 7, p = i & 127;
        ob[(size_t)o * HWSZ + p] = xm[(size_t)o * HWSZ + p] + beta2[o] * Z[o][p];
    }
}

// ---------------- launch ----------------
extern "C" void kernel_launch(void* const* d_in, const int* in_sizes, int n_in,
                              void* d_out, int out_size) {
    const float* x     = (const float*)d_in[0];
    const float* ln1w  = (const float*)d_in[1];
    const float* ln1b  = (const float*)d_in[2];
    const float* pw1w  = (const float*)d_in[3];
    const float* pw1b  = (const float*)d_in[4];
    const float* dww   = (const float*)d_in[5];
    const float* dwb   = (const float*)d_in[6];
    const float* scaw  = (const float*)d_in[7];
    const float* scab  = (const float*)d_in[8];
    const float* pw2w  = (const float*)d_in[9];
    const float* pw2b  = (const float*)d_in[10];
    const float* ln2w  = (const float*)d_in[11];
    const float* ln2b  = (const float*)d_in[12];
    const float* pw3w  = (const float*)d_in[13];
    const float* pw3b  = (const float*)d_in[14];
    const float* pw4w  = (const float*)d_in[15];
    const float* pw4b  = (const float*)d_in[16];
    const float* beta1 = (const float*)d_in[17];
    const float* beta2 = (const float*)d_in[18];
    float* out = (float*)d_out;

    cudaFuncSetAttribute(k_pw34, cudaFuncAttributeMaxDynamicSharedMemorySize, 80896);

    k_ln1  <<<NB * CC, 256>>>(x, ln1w, ln1b);
    k_pw1  <<<NB * 512, 256>>>(x, pw1w, pw1b);
    k_dw   <<<NB * 64 * 64, 256>>>(dww, dwb);
    k_sca  <<<1, 512>>>(scaw, scab);
    k_pw2  <<<NB * 512, 256>>>(x, pw2w, pw2b, beta1);
    k_ln2fin<<<1, 512>>>(ln2w, ln2b);
    k_pw34 <<<NB * 512, 256, 80896>>>(pw3w, pw3b, pw4w, pw4b, beta2, out);
}

// round 7
// speedup vs baseline: 1.5422x; 1.5422x over previous
#include <cuda_runtime.h>
#include <cuda_bf16.h>
#include <stdint.h>

#define NB   8
#define CC   64
#define HWSZ 65536   // 256*256

// ---------------- scratch (static device globals; no allocation) ----------------
__device__ __nv_bfloat16 d_t1[(size_t)NB * 128 * HWSZ];   // 128 MB: pw1 out, [n][o<128][hw]
__device__ __nv_bfloat16 d_gate[(size_t)NB * CC * HWSZ];  //  64 MB: gated dwconv out
__device__ float         d_xmid[(size_t)NB * CC * HWSZ];  // 128 MB: x + beta1*y
__device__ float d_ln1_scale[NB * CC], d_ln1_shift[NB * CC];
__device__ float d_ln2_scale[NB * CC], d_ln2_shift[NB * CC];
__device__ float d_sca_part[NB * CC * 16];                // per-(n,c) per-64x64-tile partials
__device__ float d_ln2_pS[NB * CC * 512], d_ln2_pQ[NB * CC * 512];
__device__ float d_sca_scale[NB * CC];

// ---------------- helpers ----------------
__device__ __forceinline__ void mma_bf16(float d[4], const uint32_t a[4], uint32_t b0, uint32_t b1) {
    asm volatile(
        "mma.sync.aligned.m16n8k16.row.col.f32.bf16.bf16.f32 "
        "{%0,%1,%2,%3},{%4,%5,%6,%7},{%8,%9},{%0,%1,%2,%3};\n"
        : "+f"(d[0]), "+f"(d[1]), "+f"(d[2]), "+f"(d[3])
        : "r"(a[0]), "r"(a[1]), "r"(a[2]), "r"(a[3]), "r"(b0), "r"(b1));
}
__device__ __forceinline__ uint32_t ldh2(const __nv_bfloat16* p) {
    return *reinterpret_cast<const uint32_t*>(p);
}

// ---------------- K0: ln1 stats per (n,c) ----------------
__global__ void k_ln1(const float* __restrict__ x, const float* __restrict__ w,
                      const float* __restrict__ b) {
    int nc = blockIdx.x;
    const float4* p = reinterpret_cast<const float4*>(x + (size_t)nc * HWSZ);
    float s = 0.f, q = 0.f;
    for (int i = threadIdx.x; i < HWSZ / 4; i += blockDim.x) {
        float4 v = p[i];
        s += (v.x + v.y) + (v.z + v.w);
        q += (v.x * v.x + v.y * v.y) + (v.z * v.z + v.w * v.w);
    }
    __shared__ float ss[8], sq[8];
    for (int o = 16; o; o >>= 1) {
        s += __shfl_down_sync(0xffffffffu, s, o);
        q += __shfl_down_sync(0xffffffffu, q, o);
    }
    int wid = threadIdx.x >> 5, lane = threadIdx.x & 31;
    if (!lane) { ss[wid] = s; sq[wid] = q; }
    __syncthreads();
    if (threadIdx.x == 0) {
        s = 0.f; q = 0.f;
        for (int i = 0; i < 8; i++) { s += ss[i]; q += sq[i]; }
        float mean = s * (1.f / HWSZ);
        float var  = q * (1.f / HWSZ) - mean * mean;
        float rstd = rsqrtf(var + 1e-6f);
        int c = nc & (CC - 1);
        float sc = rstd * w[c];
        d_ln1_scale[nc] = sc;
        d_ln1_shift[nc] = b[c] - mean * sc;
    }
}

// loader index remap: warp covers 4 channels x 8 pixels -> <=2-way STS conflict,
// same global sector count (neighboring halves hit L1).
__device__ __forceinline__ void remap_cp(int i, int& c, int& pl) {
    c  = ((i >> 9) << 2) + (i & 3);
    pl = (((i >> 5) & 15) << 3) + ((i >> 2) & 7);
}

// ---------------- K1: normalize -> pw1 (64 -> 128), bf16 MMA ----------------
__global__ __launch_bounds__(256) void k_pw1(const float* __restrict__ x,
                                             const float* __restrict__ w1,
                                             const float* __restrict__ bias) {
    __shared__ __align__(16) unsigned char raw[36864];
    __nv_bfloat16 (*A)[72]  = reinterpret_cast<__nv_bfloat16(*)[72]>(raw);                // 128px x 64c
    __nv_bfloat16 (*W)[72]  = reinterpret_cast<__nv_bfloat16(*)[72]>(raw + 128 * 72 * 2); // 128o x 64c
    __nv_bfloat16 (*O)[136] = reinterpret_cast<__nv_bfloat16(*)[136]>(raw);               // aliases after sync

    int tid = threadIdx.x;
    int blk = blockIdx.x;
    int n   = blk >> 9;
    int hw0 = (blk & 511) << 7;
    const float* xb = x + (size_t)n * CC * HWSZ + hw0;

    for (int i = tid; i < CC * 128; i += 256) {
        int c, pl; remap_cp(i, c, pl);
        int nc = n * CC + c;
        float v = xb[(size_t)c * HWSZ + pl];
        A[pl][c] = __float2bfloat16(fmaf(v, d_ln1_scale[nc], d_ln1_shift[nc]));
    }
    for (int i = tid; i < 128 * CC; i += 256)
        W[i >> 6][i & 63] = __float2bfloat16(w1[i]);
    __syncthreads();

    int warp = tid >> 5, lane = tid & 31, g = lane >> 2, tg = lane & 3;
    int pbase = (warp >> 1) << 5;
    int obase = (warp & 1) << 6;
    float acc[2][8][4];
#pragma unroll
    for (int mt = 0; mt < 2; mt++)
#pragma unroll
        for (int nt = 0; nt < 8; nt++)
#pragma unroll
            for (int r = 0; r < 4; r++) acc[mt][nt][r] = 0.f;

#pragma unroll
    for (int kk = 0; kk < 4; kk++) {
        int k0 = kk << 4;
        uint32_t a[2][4];
#pragma unroll
        for (int mt = 0; mt < 2; mt++) {
            const __nv_bfloat16* ap = &A[pbase + (mt << 4) + g][k0 + (tg << 1)];
            a[mt][0] = ldh2(ap);
            a[mt][1] = ldh2(ap + 8 * 72);
            a[mt][2] = ldh2(ap + 8);
            a[mt][3] = ldh2(ap + 8 * 72 + 8);
        }
#pragma unroll
        for (int nt = 0; nt < 8; nt++) {
            const __nv_bfloat16* bp = &W[obase + (nt << 3) + g][k0 + (tg << 1)];
            uint32_t b0 = ldh2(bp), b1v = ldh2(bp + 8);
            mma_bf16(acc[0][nt], a[0], b0, b1v);
            mma_bf16(acc[1][nt], a[1], b0, b1v);
        }
    }
    __syncthreads();
#pragma unroll
    for (int mt = 0; mt < 2; mt++)
#pragma unroll
        for (int nt = 0; nt < 8; nt++) {
            int p = pbase + (mt << 4) + g;
            int o = obase + (nt << 3) + (tg << 1);
            float bo0 = bias[o], bo1 = bias[o + 1];
            O[o][p]         = __float2bfloat16(acc[mt][nt][0] + bo0);
            O[o + 1][p]     = __float2bfloat16(acc[mt][nt][1] + bo1);
            O[o][p + 8]     = __float2bfloat16(acc[mt][nt][2] + bo0);
            O[o + 1][p + 8] = __float2bfloat16(acc[mt][nt][3] + bo1);
        }
    __syncthreads();
    __nv_bfloat16* t1b = d_t1 + (size_t)n * 128 * HWSZ + hw0;
    for (int i = tid; i < 128 * 32; i += 256) {
        int o = i >> 5, pp = (i & 31) << 2;
        *reinterpret_cast<uint2*>(t1b + (size_t)o * HWSZ + pp) =
            *reinterpret_cast<uint2*>(&O[o][pp]);
    }
}

// ---------------- K2: depthwise 3x3 + SimpleGate + SCA partial sums ----------------
// 64x64 tiles, fp32 smem halo, register sliding window.
__global__ __launch_bounds__(256) void k_dw(const float* __restrict__ dww,
                                            const float* __restrict__ dwb) {
    __shared__ float t0[66][68];
    __shared__ float t1s[66][68];
    __shared__ float red[8];
    int bx   = blockIdx.x;
    int tile = bx & 15;
    int c    = (bx >> 4) & 63;
    int n    = bx >> 10;
    int gx0  = (tile & 3) << 6, gy0 = (tile >> 2) << 6;
    int tid  = threadIdx.x;
    const __nv_bfloat16* p0 = d_t1 + (size_t)(n * 128 + c) * HWSZ;
    const __nv_bfloat16* p1 = p0 + (size_t)64 * HWSZ;

    for (int i = tid; i < 2 * 66 * 66; i += 256) {
        int ch  = i >= 4356;
        int rem = ch ? i - 4356 : i;
        int r   = rem / 66;
        int col = rem - r * 66;
        int gy = gy0 + r - 1, gx = gx0 + col - 1;
        float v = 0.f;
        if ((unsigned)gy < 256u && (unsigned)gx < 256u)
            v = __bfloat162float((ch ? p1 : p0)[gy * 256 + gx]);
        (ch ? t1s : t0)[r][col] = v;
    }
    float w0[9], w1[9];
#pragma unroll
    for (int k = 0; k < 9; k++) {
        w0[k] = dww[c * 9 + k];
        w1[k] = dww[(c + 64) * 9 + k];
    }
    float db0 = dwb[c], db1 = dwb[c + 64];
    __syncthreads();

    int tx = tid & 63, tyb = tid >> 6;
    int ty0 = tyb << 4;
    float psum = 0.f;
    __nv_bfloat16* gout = d_gate + (size_t)(n * 64 + c) * HWSZ;

    float x0a = t0[ty0][tx],     x0b = t0[ty0][tx + 1],     x0c = t0[ty0][tx + 2];
    float x1a = t0[ty0 + 1][tx], x1b = t0[ty0 + 1][tx + 1], x1c = t0[ty0 + 1][tx + 2];
    float y0a = t1s[ty0][tx],     y0b = t1s[ty0][tx + 1],     y0c = t1s[ty0][tx + 2];
    float y1a = t1s[ty0 + 1][tx], y1b = t1s[ty0 + 1][tx + 1], y1c = t1s[ty0 + 1][tx + 2];
#pragma unroll
    for (int j = 0; j < 16; j++) {
        int r2 = ty0 + j + 2;
        float x2a = t0[r2][tx], x2b = t0[r2][tx + 1], x2c = t0[r2][tx + 2];
        float y2a = t1s[r2][tx], y2b = t1s[r2][tx + 1], y2c = t1s[r2][tx + 2];
        float s0 = db0;
        s0 = fmaf(x0a, w0[0], s0); s0 = fmaf(x0b, w0[1], s0); s0 = fmaf(x0c, w0[2], s0);
        s0 = fmaf(x1a, w0[3], s0); s0 = fmaf(x1b, w0[4], s0); s0 = fmaf(x1c, w0[5], s0);
        s0 = fmaf(x2a, w0[6], s0); s0 = fmaf(x2b, w0[7], s0); s0 = fmaf(x2c, w0[8], s0);
        float s1 = db1;
        s1 = fmaf(y0a, w1[0], s1); s1 = fmaf(y0b, w1[1], s1); s1 = fmaf(y0c, w1[2], s1);
        s1 = fmaf(y1a, w1[3], s1); s1 = fmaf(y1b, w1[4], s1); s1 = fmaf(y1c, w1[5], s1);
        s1 = fmaf(y2a, w1[6], s1); s1 = fmaf(y2b, w1[7], s1); s1 = fmaf(y2c, w1[8], s1);
        float v = s0 * s1;
        psum += v;
        gout[(gy0 + ty0 + j) * 256 + gx0 + tx] = __float2bfloat16(v);
        x0a = x1a; x0b = x1b; x0c = x1c; x1a = x2a; x1b = x2b; x1c = x2c;
        y0a = y1a; y0b = y1b; y0c = y1c; y1a = y2a; y1b = y2b; y1c = y2c;
    }
    for (int o = 16; o; o >>= 1) psum += __shfl_down_sync(0xffffffffu, psum, o);
    int lane = tid & 31, wid = tid >> 5;
    if (!lane) red[wid] = psum;
    __syncthreads();
    if (tid == 0) {
        float t = 0.f;
        for (int i = 0; i < 8; i++) t += red[i];
        d_sca_part[(n * 64 + c) * 16 + tile] = t;
    }
}

// ---------------- K3: SCA  sigmoid(W s + b), one block per n ----------------
__global__ void k_sca(const float* __restrict__ sw, const float* __restrict__ sb) {
    __shared__ float s[64];
    int n = blockIdx.x, c = threadIdx.x;   // 64 threads
    float t = 0.f;
    const float* p = d_sca_part + (n * 64 + c) * 16;
    for (int i = 0; i < 16; i++) t += p[i];
    s[c] = t * (1.f / HWSZ);
    __syncthreads();
    float acc = sb[c];
    const float* wr = sw + c * 64;
    for (int k = 0; k < 64; k++) acc = fmaf(wr[k], s[k], acc);
    d_sca_scale[n * 64 + c] = 1.f / (1.f + expf(-acc));
}

// ---------------- K4: scale -> pw2 (64->64) -> residual -> xmid + ln2 partials ----------------
__global__ __launch_bounds__(256) void k_pw2(const float* __restrict__ x,
                                             const float* __restrict__ w2,
                                             const float* __restrict__ b2,
                                             const float* __restrict__ beta1) {
    __shared__ __align__(16) unsigned char raw[33792];
    __nv_bfloat16 (*A)[72] = reinterpret_cast<__nv_bfloat16(*)[72]>(raw);                // 128px x 64c
    __nv_bfloat16 (*W)[72] = reinterpret_cast<__nv_bfloat16(*)[72]>(raw + 128 * 72 * 2); // 64o x 64c
    float (*O)[132]        = reinterpret_cast<float(*)[132]>(raw);                       // aliases after sync
    __shared__ float psA[64][4], psB[64][4];

    int tid = threadIdx.x;
    int blk = blockIdx.x;
    int n   = blk >> 9;
    int hw0 = (blk & 511) << 7;

    for (int i = tid; i < 64 * 128; i += 256) {
        int c, pl; remap_cp(i, c, pl);
        float v = __bfloat162float(d_gate[(size_t)(n * 64 + c) * HWSZ + hw0 + pl]) *
                  d_sca_scale[n * 64 + c];
        A[pl][c] = __float2bfloat16(v);
    }
    for (int i = tid; i < 64 * 64; i += 256)
        W[i >> 6][i & 63] = __float2bfloat16(w2[i]);
    __syncthreads();

    int warp = tid >> 5, lane = tid & 31, g = lane >> 2, tg = lane & 3;
    int pbase = (warp >> 1) << 5;
    int obase = (warp & 1) << 5;
    float acc[2][4][4];
#pragma unroll
    for (int mt = 0; mt < 2; mt++)
#pragma unroll
        for (int nt = 0; nt < 4; nt++)
#pragma unroll
            for (int r = 0; r < 4; r++) acc[mt][nt][r] = 0.f;

#pragma unroll
    for (int kk = 0; kk < 4; kk++) {
        int k0 = kk << 4;
        uint32_t a[2][4];
#pragma unroll
        for (int mt = 0; mt < 2; mt++) {
            const __nv_bfloat16* ap = &A[pbase + (mt << 4) + g][k0 + (tg << 1)];
            a[mt][0] = ldh2(ap);
            a[mt][1] = ldh2(ap + 8 * 72);
            a[mt][2] = ldh2(ap + 8);
            a[mt][3] = ldh2(ap + 8 * 72 + 8);
        }
#pragma unroll
        for (int nt = 0; nt < 4; nt++) {
            const __nv_bfloat16* bp = &W[obase + (nt << 3) + g][k0 + (tg << 1)];
            uint32_t b0 = ldh2(bp), b1v = ldh2(bp + 8);
            mma_bf16(acc[0][nt], a[0], b0, b1v);
            mma_bf16(acc[1][nt], a[1], b0, b1v);
        }
    }
    __syncthreads();
#pragma unroll
    for (int mt = 0; mt < 2; mt++)
#pragma unroll
        for (int nt = 0; nt < 4; nt++) {
            int p = pbase + (mt << 4) + g;
            int o = obase + (nt << 3) + (tg << 1);
            O[o][p]         = acc[mt][nt][0] + b2[o];
            O[o + 1][p]     = acc[mt][nt][1] + b2[o + 1];
            O[o][p + 8]     = acc[mt][nt][2] + b2[o];
            O[o + 1][p + 8] = acc[mt][nt][3] + b2[o + 1];
        }
    __syncthreads();
    const float* xb = x + (size_t)n * 64 * HWSZ + hw0;
    float* xm = d_xmid + (size_t)n * 64 * HWSZ + hw0;
    for (int i = tid; i < 64 * 32; i += 256) {
        int o = i >> 5, p = (i & 31) << 2;
        float4 xv = *reinterpret_cast<const float4*>(xb + (size_t)o * HWSZ + p);
        float bo = beta1[o];
        float4 r;
        r.x = xv.x + bo * O[o][p];
        r.y = xv.y + bo * O[o][p + 1];
        r.z = xv.z + bo * O[o][p + 2];
        r.w = xv.w + bo * O[o][p + 3];
        *reinterpret_cast<float4*>(xm + (size_t)o * HWSZ + p) = r;
        O[o][p] = r.x; O[o][p + 1] = r.y; O[o][p + 2] = r.z; O[o][p + 3] = r.w;
    }
    __syncthreads();
    {
        int o = tid >> 2, seg = (tid & 3) << 5;
        float s = 0.f, q = 0.f;
        for (int j = 0; j < 32; j++) {
            float v = O[o][seg + j];
            s += v; q += v * v;
        }
        psA[o][tid & 3] = s; psB[o][tid & 3] = q;
    }
    __syncthreads();
    if (tid < 64) {
        float s = psA[tid][0] + psA[tid][1] + psA[tid][2] + psA[tid][3];
        float q = psB[tid][0] + psB[tid][1] + psB[tid][2] + psB[tid][3];
        size_t slot = (size_t)(n * 64 + tid) * 512 + (blk & 511);
        d_ln2_pS[slot] = s;
        d_ln2_pQ[slot] = q;
    }
}

// ---------------- K5: ln2 finalize, one block per (n,c) ----------------
__global__ void k_ln2fin(const float* __restrict__ w, const float* __restrict__ b) {
    int nc = blockIdx.x;
    int tid = threadIdx.x;  // 128
    float s = 0.f, q = 0.f;
    const float* pS = d_ln2_pS + (size_t)nc * 512;
    const float* pQ = d_ln2_pQ + (size_t)nc * 512;
    for (int i = tid; i < 512; i += 128) { s += pS[i]; q += pQ[i]; }
    __shared__ float ss[4], sq[4];
    for (int o = 16; o; o >>= 1) {
        s += __shfl_down_sync(0xffffffffu, s, o);
        q += __shfl_down_sync(0xffffffffu, q, o);
    }
    int wid = tid >> 5, lane = tid & 31;
    if (!lane) { ss[wid] = s; sq[wid] = q; }
    __syncthreads();
    if (tid == 0) {
        s = ss[0] + ss[1] + ss[2] + ss[3];
        q = sq[0] + sq[1] + sq[2] + sq[3];
        float mean = s * (1.f / HWSZ);
        float var  = q * (1.f / HWSZ) - mean * mean;
        float rstd = rsqrtf(var + 1e-6f);
        int c = nc & 63;
        float sc = rstd * w[c];
        d_ln2_scale[nc] = sc;
        d_ln2_shift[nc] = b[c] - mean * sc;
    }
}

// ---------------- K6: normalize -> pw3 -> gate -> pw4 -> residual -> out ----------------
__global__ __launch_bounds__(256) void k_pw34(const float* __restrict__ w3,
                                              const float* __restrict__ b3,
                                              const float* __restrict__ w4,
                                              const float* __restrict__ b4,
                                              const float* __restrict__ beta2,
                                              float* __restrict__ out) {
    extern __shared__ __align__(16) unsigned char dyn[];
    __nv_bfloat16 (*W3)[72] = reinterpret_cast<__nv_bfloat16(*)[72]>(dyn);            // 128o x 64c
    __nv_bfloat16 (*W4)[72] = reinterpret_cast<__nv_bfloat16(*)[72]>(dyn + 18432);    // 64o x 64c
    __nv_bfloat16 (*A)[72]  = reinterpret_cast<__nv_bfloat16(*)[72]>(dyn + 27648);    // 128px x 64c
    __nv_bfloat16 (*U)[136] = reinterpret_cast<__nv_bfloat16(*)[136]>(dyn + 46080);   // 128px x 128o
    float (*Z)[132]         = reinterpret_cast<float(*)[132]>(dyn + 46080);           // aliases U

    int tid = threadIdx.x;
    int blk = blockIdx.x;
    int n   = blk >> 9;
    int hw0 = (blk & 511) << 7;
    const float* xm = d_xmid + (size_t)n * 64 * HWSZ + hw0;

    for (int i = tid; i < 128 * 64; i += 256) W3[i >> 6][i & 63] = __float2bfloat16(w3[i]);
    for (int i = tid; i < 64 * 64; i += 256)  W4[i >> 6][i & 63] = __float2bfloat16(w4[i]);
    for (int i = tid; i < 64 * 128; i += 256) {
        int c, pl; remap_cp(i, c, pl);
        int nc = n * 64 + c;
        A[pl][c] = __float2bfloat16(fmaf(xm[(size_t)c * HWSZ + pl], d_ln2_scale[nc], d_ln2_shift[nc]));
    }
    __syncthreads();

    int warp = tid >> 5, lane = tid & 31, g = lane >> 2, tg = lane & 3;
    int pbase = (warp >> 1) << 5;
    int obase = (warp & 1) << 6;

    // ---- GEMM1: u = A @ W3^T  (128px x 128out) ----
    {
        float acc[2][8][4];
#pragma unroll
        for (int mt = 0; mt < 2; mt++)
#pragma unroll
            for (int nt = 0; nt < 8; nt++)
#pragma unroll
                for (int r = 0; r < 4; r++) acc[mt][nt][r] = 0.f;
#pragma unroll
        for (int kk = 0; kk < 4; kk++) {
            int k0 = kk << 4;
            uint32_t a[2][4];
#pragma unroll
            for (int mt = 0; mt < 2; mt++) {
                const __nv_bfloat16* ap = &A[pbase + (mt << 4) + g][k0 + (tg << 1)];
                a[mt][0] = ldh2(ap);
                a[mt][1] = ldh2(ap + 8 * 72);
                a[mt][2] = ldh2(ap + 8);
                a[mt][3] = ldh2(ap + 8 * 72 + 8);
            }
#pragma unroll
            for (int nt = 0; nt < 8; nt++) {
                const __nv_bfloat16* bp = &W3[obase + (nt << 3) + g][k0 + (tg << 1)];
                uint32_t b0 = ldh2(bp), b1v = ldh2(bp + 8);
                mma_bf16(acc[0][nt], a[0], b0, b1v);
                mma_bf16(acc[1][nt], a[1], b0, b1v);
            }
        }
        __syncthreads();
#pragma unroll
        for (int mt = 0; mt < 2; mt++)
#pragma unroll
            for (int nt = 0; nt < 8; nt++) {
                int p = pbase + (mt << 4) + g;
                int o = obase + (nt << 3) + (tg << 1);
                float bo0 = b3[o], bo1 = b3[o + 1];
                __nv_bfloat162 lo, hi;
                lo.x = __float2bfloat16(acc[mt][nt][0] + bo0);
                lo.y = __float2bfloat16(acc[mt][nt][1] + bo1);
                hi.x = __float2bfloat16(acc[mt][nt][2] + bo0);
                hi.y = __float2bfloat16(acc[mt][nt][3] + bo1);
                *reinterpret_cast<__nv_bfloat162*>(&U[p][o])     = lo;
                *reinterpret_cast<__nv_bfloat162*>(&U[p + 8][o]) = hi;
            }
    }
    __syncthreads();

    // ---- GEMM2: z = gate(U) @ W4^T  (128px x 64out), gate fused into fragment build ----
    int obase2 = (warp & 1) << 5;
    float acc2[2][4][4];
#pragma unroll
    for (int mt = 0; mt < 2; mt++)
#pragma unroll
        for (int nt = 0; nt < 4; nt++)
#pragma unroll
            for (int r = 0; r < 4; r++) acc2[mt][nt][r] = 0.f;
#pragma unroll
    for (int kk = 0; kk < 4; kk++) {
        int k0 = kk << 4;
        uint32_t a2[2][4];
#pragma unroll
        for (int mt = 0; mt < 2; mt++) {
            int p = pbase + (mt << 4) + g;
            const __nv_bfloat16* r0 = &U[p][k0 + (tg << 1)];
            const __nv_bfloat16* r1 = &U[p + 8][k0 + (tg << 1)];
            __nv_bfloat162 v;
            v = __hmul2(*reinterpret_cast<const __nv_bfloat162*>(r0),
                        *reinterpret_cast<const __nv_bfloat162*>(r0 + 64));
            a2[mt][0] = *reinterpret_cast<uint32_t*>(&v);
            v = __hmul2(*reinterpret_cast<const __nv_bfloat162*>(r1),
                        *reinterpret_cast<const __nv_bfloat162*>(r1 + 64));
            a2[mt][1] = *reinterpret_cast<uint32_t*>(&v);
            v = __hmul2(*reinterpret_cast<const __nv_bfloat162*>(r0 + 8),
                        *reinterpret_cast<const __nv_bfloat162*>(r0 + 72));
            a2[mt][2] = *reinterpret_cast<uint32_t*>(&v);
            v = __hmul2(*reinterpret_cast<const __nv_bfloat162*>(r1 + 8),
                        *reinterpret_cast<const __nv_bfloat162*>(r1 + 72));
            a2[mt][3] = *reinterpret_cast<uint32_t*>(&v);
        }
#pragma unroll
        for (int nt = 0; nt < 4; nt++) {
            const __nv_bfloat16* bp = &W4[obase2 + (nt << 3) + g][k0 + (tg << 1)];
            uint32_t b0 = ldh2(bp), b1v = ldh2(bp + 8);
            mma_bf16(acc2[0][nt], a2[0], b0, b1v);
            mma_bf16(acc2[1][nt], a2[1], b0, b1v);
        }
    }
    __syncthreads();  // all U reads done before Z (alias) overwrite
#pragma unroll
    for (int mt = 0; mt < 2; mt++)
#pragma unroll
        for (int nt = 0; nt < 4; nt++) {
            int p = pbase + (mt << 4) + g;
            int o = obase2 + (nt << 3) + (tg << 1);
            Z[o][p]         = acc2[mt][nt][0] + b4[o];
            Z[o + 1][p]     = acc2[mt][nt][1] + b4[o + 1];
            Z[o][p + 8]     = acc2[mt][nt][2] + b4[o];
            Z[o + 1][p + 8] = acc2[mt][nt][3] + b4[o + 1];
        }
    __syncthreads();
    float* ob = out + (size_t)n * 64 * HWSZ + hw0;
    for (int i = tid; i < 64 * 32; i += 256) {
        int o = i >> 5, p = (i & 31) << 2;
        float4 xv = *reinterpret_cast<const float4*>(xm + (size_t)o * HWSZ + p);
        float bo = beta2[o];
        float4 r;
        r.x = xv.x + bo * Z[o][p];
        r.y = xv.y + bo * Z[o][p + 1];
        r.z = xv.z + bo * Z[o][p + 2];
        r.w = xv.w + bo * Z[o][p + 3];
        *reinterpret_cast<float4*>(ob + (size_t)o * HWSZ + p) = r;
    }
}

// ---------------- launch ----------------
extern "C" void kernel_launch(void* const* d_in, const int* in_sizes, int n_in,
                              void* d_out, int out_size) {
    const float* x     = (const float*)d_in[0];
    const float* ln1w  = (const float*)d_in[1];
    const float* ln1b  = (const float*)d_in[2];
    const float* pw1w  = (const float*)d_in[3];
    const float* pw1b  = (const float*)d_in[4];
    const float* dww   = (const float*)d_in[5];
    const float* dwb   = (const float*)d_in[6];
    const float* scaw  = (const float*)d_in[7];
    const float* scab  = (const float*)d_in[8];
    const float* pw2w  = (const float*)d_in[9];
    const float* pw2b  = (const float*)d_in[10];
    const float* ln2w  = (const float*)d_in[11];
    const float* ln2b  = (const float*)d_in[12];
    const float* pw3w  = (const float*)d_in[13];
    const float* pw3b  = (const float*)d_in[14];
    const float* pw4w  = (const float*)d_in[15];
    const float* pw4b  = (const float*)d_in[16];
    const float* beta1 = (const float*)d_in[17];
    const float* beta2 = (const float*)d_in[18];
    float* out = (float*)d_out;

    cudaFuncSetAttribute(k_pw34, cudaFuncAttributeMaxDynamicSharedMemorySize, 80896);

    k_ln1   <<<NB * CC, 256>>>(x, ln1w, ln1b);
    k_pw1   <<<NB * 512, 256>>>(x, pw1w, pw1b);
    k_dw    <<<NB * 64 * 16, 256>>>(dww, dwb);
    k_sca   <<<NB, 64>>>(scaw, scab);
    k_pw2   <<<NB * 512, 256>>>(x, pw2w, pw2b, beta1);
    k_ln2fin<<<NB * CC, 128>>>(ln2w, ln2b);
    k_pw34  <<<NB * 512, 256, 80896>>>(pw3w, pw3b, pw4w, pw4b, beta2, out);
}